// round 5
// baseline (speedup 1.0000x reference)
#include <cuda_runtime.h>
#include <cstdint>

#define NSTEPS   730
#define NGRID    8000
#define UHL      15
#define CH       10          // timesteps per smem chunk; 730 = 73 * 10
#define BT       64          // threads (cells) per block in recurrence kernel
#define NCHUNK   (NSTEPS / CH)
#define NEARZERO 1e-5f
#define TTILE    16          // t-steps per thread in routing kernel

// scratch: Q series planar [series][t*NGRID+g], plus UH weights [k*NGRID+g]
__device__ float qbuf[3][NSTEPS * NGRID];
__device__ float wbuf[UHL * NGRID];

__device__ __forceinline__ float sigmoidf_(float x) {
    return 1.0f / (1.0f + __expf(-x));
}

__device__ __forceinline__ uint32_t smem_u32(const void* p) {
    uint32_t a;
    asm("{ .reg .u64 t; cvta.to.shared.u64 t, %1; cvt.u32.u64 %0, t; }" : "=r"(a) : "l"(p));
    return a;
}
__device__ __forceinline__ void cp_async16(uint32_t dst, const void* src) {
    asm volatile("cp.async.ca.shared.global [%0], [%1], 16;\n" :: "r"(dst), "l"(src));
}
__device__ __forceinline__ void cp_commit() { asm volatile("cp.async.commit_group;\n"); }
__device__ __forceinline__ void cp_wait1() { asm volatile("cp.async.wait_group 1;\n"); }

// ---------------------------------------------------------------------------
// Kernel 0: gamma unit-hydrograph weights per cell
// ---------------------------------------------------------------------------
__global__ void w_kernel(const float* __restrict__ params) {
    const int g = blockIdx.x * blockDim.x + threadIdx.x;
    if (g >= NGRID) return;
    const float* pr = params + ((size_t)(NSTEPS - 1) * NGRID + (size_t)g) * 16;
    float4 r3 = *(const float4*)(pr + 12);
    const float route_a = sigmoidf_(r3.z) * 2.9f;
    const float route_b = sigmoidf_(r3.w) * 6.5f;
    const float aa    = fmaxf(route_a, 0.0f) + 0.1f;
    const float theta = fmaxf(route_b, 0.0f) + 0.5f;
    const float am1   = aa - 1.0f;
    const float invth = __fdividef(1.0f, theta);
    float w[UHL], wsum = 0.0f;
    #pragma unroll
    for (int k = 0; k < UHL; k++) {
        float tk = (float)k + 0.5f;
        float v  = __expf(am1 * __logf(tk) - tk * invth);  // Gamma(a)*theta^a cancels
        w[k] = v;
        wsum += v;
    }
    const float inv_wsum = __fdividef(1.0f, wsum);
    #pragma unroll
    for (int k = 0; k < UHL; k++) wbuf[k * NGRID + g] = w[k] * inv_wsum;
}

// ---------------------------------------------------------------------------
// Kernel 1: serial HBV recurrence, emits Q0/Q1/Q2 per step (no conv, no UH)
// ---------------------------------------------------------------------------
__shared__ float sbuf[2][CH][BT * 3];

__device__ __forceinline__ void issue_chunk(const float* __restrict__ xphy,
                                            int c, int pb, int g0, int tid,
                                            uint32_t sbase) {
    const int t0 = c * CH;
    const float* src_base = xphy + (size_t)t0 * (NGRID * 3) + (size_t)g0 * 3;
    constexpr int ROW16 = BT * 3 / 4;        // 48 16B units per row
    constexpr int TOT16 = CH * ROW16;        // 480
    #pragma unroll 1
    for (int idx = tid; idx < TOT16; idx += BT) {
        int row = idx / ROW16;
        int col = idx - row * ROW16;
        const float* src = src_base + (size_t)row * (NGRID * 3) + col * 4;
        uint32_t dst = sbase + (uint32_t)(((pb * CH + row) * (BT * 3) + col * 4) * 4);
        cp_async16(dst, src);
    }
    cp_commit();
}

__global__ __launch_bounds__(BT, 1)
void hbv_step_kernel(const float* __restrict__ xphy,
                     const float* __restrict__ params)
{
    const int tid = threadIdx.x;
    const int g0  = blockIdx.x * BT;
    const int g   = g0 + tid;
    const uint32_t sbase = smem_u32(&sbuf[0][0][0]);

    const float* pr = params + ((size_t)(NSTEPS - 1) * NGRID + (size_t)g) * 16;
    float4 r0 = *(const float4*)(pr + 0);
    float4 r1 = *(const float4*)(pr + 4);
    float4 r2 = *(const float4*)(pr + 8);
    float4 r3 = *(const float4*)(pr + 12);

    const float parBETA   = 1.0f   + sigmoidf_(r0.x) * 5.0f;
    const float parFC     = 50.0f  + sigmoidf_(r0.y) * 950.0f;
    const float parK0     = 0.05f  + sigmoidf_(r0.z) * 0.85f;
    const float parK1     = 0.01f  + sigmoidf_(r0.w) * 0.49f;
    const float parK2     = 0.001f + sigmoidf_(r1.x) * 0.199f;
    const float parLP     = 0.2f   + sigmoidf_(r1.y) * 0.8f;
    const float parPERC   =          sigmoidf_(r1.z) * 10.0f;
    const float parUZL    =          sigmoidf_(r1.w) * 100.0f;
    const float parTT     = -2.5f  + sigmoidf_(r2.x) * 5.0f;
    const float parCFMAX  = 0.5f   + sigmoidf_(r2.y) * 9.5f;
    const float cfr_cfmax =          sigmoidf_(r2.z) * 0.1f * parCFMAX;
    const float parCWH    =          sigmoidf_(r2.w) * 0.2f;
    const float parBETAET = 0.3f   + sigmoidf_(r3.x) * 4.7f;
    const float parC      =          sigmoidf_(r3.y);

    const float inv_fc   = __fdividef(1.0f, parFC);
    const float inv_lpfc = __fdividef(1.0f, parLP * parFC);

    float SNOWPACK = 0.001f, MELTWATER = 0.001f, SM = 0.001f, SUZ = 0.001f, SLZ = 0.001f;

    issue_chunk(xphy, 0, 0, g0, tid, sbase);
    issue_chunk(xphy, 1, 1, g0, tid, sbase);

    float* __restrict__ q0p = &qbuf[0][g];
    float* __restrict__ q1p = &qbuf[1][g];
    float* __restrict__ q2p = &qbuf[2][g];
    const int s3 = tid * 3;

    for (int k = 0; k < NCHUNK; k++) {
        const int pb = k & 1;
        cp_wait1();
        __syncthreads();

        #pragma unroll
        for (int u = 0; u < CH; u++) {
            const float P   = sbuf[pb][u][s3 + 0];
            const float Tt  = sbuf[pb][u][s3 + 1];
            const float PET = sbuf[pb][u][s3 + 2];

            // ---- SM critical chain head ----
            const float sw = fminf(__expf(parBETA * __logf(SM * inv_fc)), 1.0f);

            // ---- snow (parallel branch) ----
            const float RAIN = (Tt >= parTT) ? P : 0.0f;
            const float SNOW = (Tt <  parTT) ? P : 0.0f;
            float sp = SNOWPACK + SNOW;
            const float melt = fminf(fmaxf(parCFMAX * (Tt - parTT), 0.0f), sp);
            float mw = MELTWATER + melt;
            sp -= melt;
            const float refreeze = fminf(fmaxf(cfr_cfmax * (parTT - Tt), 0.0f), mw);
            sp += refreeze;
            mw -= refreeze;
            const float tosoil = fmaxf(mw - parCWH * sp, 0.0f);
            MELTWATER = mw - tosoil;
            SNOWPACK  = sp;

            // ---- soil moisture ----
            const float rt   = RAIN + tosoil;
            const float smrt = SM + rt;
            const float recharge = rt * sw;
            const float SM1 = fmaf(-rt, sw, smrt);
            const float excess = fmaxf(SM1 - parFC, 0.0f);
            const float SM2 = fminf(SM1, parFC);
            // capillary (min-with-SLZ redundant: C<=1 and SM2<=FC)
            const float cSLZ = parC * SLZ;
            const float cap  = cSLZ * fmaf(-inv_fc, SM2, 1.0f);
            const float SM3  = fmaxf(SM2 + cap, NEARZERO);
            const float SLZa = fmaxf(SLZ - cap, NEARZERO);

            // ---- evapotranspiration ----
            const float evr = fminf(SM3 * inv_lpfc, 1.0f);
            const float ef  = __expf(parBETAET * __logf(evr));
            const float ET  = fminf(PET * ef, SM3);
            SM = fmaxf(SM3 - ET, NEARZERO);

            // ---- response routine ----
            float suz = SUZ + recharge + excess;
            const float perc = fminf(suz, parPERC);
            suz -= perc;
            const float Q0 = parK0 * fmaxf(suz - parUZL, 0.0f);
            suz -= Q0;
            const float Q1 = parK1 * suz;
            SUZ = suz - Q1;
            float slz = SLZa + perc;
            const float Q2 = parK2 * slz;
            SLZ = slz - Q2;

            const int t = k * CH + u;
            q0p[(size_t)t * NGRID] = Q0;
            q1p[(size_t)t * NGRID] = Q1;
            q2p[(size_t)t * NGRID] = Q2;
        }

        __syncthreads();
        if (k + 2 < NCHUNK)
            issue_chunk(xphy, k + 2, pb, g0, tid, sbase);
        else
            cp_commit();
    }
}

// ---------------------------------------------------------------------------
// Kernel 2: fully parallel 15-tap causal convolution (routing)
// thread = one cell g, one tile of TTILE consecutive timesteps
// ---------------------------------------------------------------------------
__global__ __launch_bounds__(64)
void route_kernel(float* __restrict__ out)
{
    const int g  = blockIdx.x * 64 + threadIdx.x;
    const int t0 = blockIdx.y * TTILE;

    float w[UHL];
    #pragma unroll
    for (int k = 0; k < UHL; k++) w[k] = wbuf[k * NGRID + g];

    float y0[TTILE], y1[TTILE], y2[TTILE];

    #pragma unroll
    for (int s = 0; s < 3; s++) {
        const float* __restrict__ q = qbuf[s];
        float r[TTILE + UHL - 1];
        #pragma unroll
        for (int i = 0; i < TTILE + UHL - 1; i++) {
            const int t = t0 - (UHL - 1) + i;
            r[i] = (t >= 0 && t < NSTEPS) ? q[(size_t)t * NGRID + g] : 0.0f;
        }
        float* y = (s == 0) ? y0 : (s == 1) ? y1 : y2;
        #pragma unroll
        for (int u = 0; u < TTILE; u++) {
            float acc = 0.0f;
            #pragma unroll
            for (int k = 0; k < UHL; k++)
                acc = fmaf(w[k], r[u + UHL - 1 - k], acc);
            y[u] = acc;
        }
    }

    float4* __restrict__ out4 = (float4*)out;
    #pragma unroll
    for (int u = 0; u < TTILE; u++) {
        const int t = t0 + u;
        if (t < NSTEPS) {
            float4 o;
            o.x = y0[u] + y1[u] + y2[u];
            o.y = y0[u];
            o.z = y1[u];
            o.w = y2[u];
            out4[(size_t)t * NGRID + g] = o;
        }
    }
}

// ---------------------------------------------------------------------------
extern "C" void kernel_launch(void* const* d_in, const int* in_sizes, int n_in,
                              void* d_out, int out_size) {
    const float* xphy   = (const float*)d_in[0];   // [730, 8000, 3]
    const float* params = (const float*)d_in[1];   // [730, 8000, 16]
    float* out = (float*)d_out;                    // [730, 8000, 4]
    (void)in_sizes; (void)n_in; (void)out_size;

    w_kernel<<<NGRID / 64, 64>>>(params);
    hbv_step_kernel<<<NGRID / BT, BT>>>(xphy, params);
    dim3 rgrid(NGRID / 64, (NSTEPS + TTILE - 1) / TTILE);
    route_kernel<<<rgrid, 64>>>(out);
}